// round 3
// baseline (speedup 1.0000x reference)
#include <cuda_runtime.h>
#include <math.h>

#define NT    512
#define NBLK  592
#define BATCH 50000
#define NPAIR ((BATCH + 1) / 2)

typedef unsigned long long u64;

// ---- shared memory layout (float offsets, all even where float2 is used) ----
#define OFF_SFT  0            // sft transposed: SFT[p*48 + k], 90 x 48, zero for k>=45
#define OFF_ISF  4320         // isft transposed: ISF[k*92 + p], 45 x 92
#define OFF_SC   8460         // scale[45] (+pad to 48)
#define OFF_W    8508         // weights, padded rows (26404 floats)
#define OFF_A    34912        // x buffer  [2][64][50]
#define OFF_B    41312        // t buffer  [2][64][50]
#define OFF_SIG  47712        // sig       [2][32][92]
#define SMEM_FLOATS 53600
#define SMEM_BYTES  (SMEM_FLOATS * 4)

// per-layer weight offsets inside OFF_W, row stride RS = Cin*5 + 1
#define WOFF1 0        // 16 x 21
#define WOFF2 336      // 32 x 81
#define WOFF3 2928     // 64 x 161
#define WOFF4 13232    // 32 x 321
#define WOFF5 23504    // 16 x 161
#define WOFF6 26080    // 4  x 81

static_assert(OFF_SIG + 2 * 32 * 92 == SMEM_FLOATS, "smem layout");

// packed fp32x2 helpers (Blackwell FFMA2 path)
__device__ __forceinline__ u64 fma2(u64 a, u64 b, u64 c) {
    u64 d;
    asm("fma.rn.f32x2 %0, %1, %2, %3;" : "=l"(d) : "l"(a), "l"(b), "l"(c));
    return d;
}
__device__ __forceinline__ u64 pack2(float v) {
    u64 d;
    asm("mov.b64 %0, {%1, %1};" : "=l"(d) : "f"(v));
    return d;
}
__device__ __forceinline__ float2 unpack2(u64 v) {
    float2 r;
    asm("mov.b64 {%0, %1}, %2;" : "=f"(r.x), "=f"(r.y) : "l"(v));
    return r;
}

// sconv k-tiles aligned to degree-group boundaries (single ls_idx per tile)
__constant__ int c_tk0[15] = {0, 1, 5, 6, 10, 14, 15, 19, 23, 27, 28, 32, 36, 40, 44};
__constant__ int c_tkl[15] = {1, 4, 1, 4, 4, 1, 4, 4, 4, 1, 4, 4, 4, 4, 1};
__constant__ int c_td[15]  = {0, 1, 1, 2, 2, 2, 3, 3, 3, 3, 4, 4, 4, 4, 4};

// sconv: t[bi][o][k] = scale[k] * sum_c x[bi][c][k] * W[o][c][d(k)]   (scalar fp32)
template <int Cin, int Cout, int WOFF, int RS>
__device__ __forceinline__ void sconv_step(float* sm, int tid)
{
    constexpr int NO4 = Cout / 4;
    constexpr int SLOTS = 2 * NO4 * 15;
    if (tid < SLOTS) {
        const int kt = tid % 15;
        const int bi = (tid / 15) & 1;
        const int ot = tid / 30;
        const int k0   = c_tk0[kt];
        const int klen = c_tkl[kt];
        const int d    = c_td[kt];
        const float* __restrict__ A = sm + OFF_A + (bi * 64) * 50 + k0;
        const float* __restrict__ W = sm + OFF_W + WOFF + (ot * 4) * RS + d;

        float acc[4][4];
#pragma unroll
        for (int i = 0; i < 4; i++)
#pragma unroll
            for (int j = 0; j < 4; j++) acc[i][j] = 0.f;

#pragma unroll 4
        for (int c = 0; c < Cin; c++) {
            float xv[4];
#pragma unroll
            for (int j = 0; j < 4; j++) xv[j] = A[c * 50 + j];   // k0+3 <= 47 < 50 safe
#pragma unroll
            for (int i = 0; i < 4; i++) {
                float w = W[i * RS + c * 5];
#pragma unroll
                for (int j = 0; j < 4; j++) acc[i][j] = fmaf(w, xv[j], acc[i][j]);
            }
        }

        float* __restrict__ B = sm + OFF_B + (bi * 64 + ot * 4) * 50 + k0;
#pragma unroll
        for (int i = 0; i < 4; i++)
#pragma unroll
            for (int j = 0; j < 4; j++)
                if (j < klen) B[i * 50 + j] = acc[i][j] * sm[OFF_SC + k0 + j];
    }
}

// GEMM1 (f32x2): sig[bi][c][p0..p0+5] = relu( sum_k t[bi][c][k] * isft[p][k] )
// tiles: 15 p-tiles of 6 (3 float2 pairs) x CT channels
template <int NCH, int CT>
__device__ __forceinline__ void gemm1_step(float* sm, int ch0, int tid)
{
    constexpr int SLOTS = 2 * (NCH / CT) * 15;
    if (tid < SLOTS) {
        const int pt = tid % 15;
        const int bi = (tid / 15) & 1;
        const int ct = tid / 30;
        const float* __restrict__ T  = sm + OFF_B + (bi * 64 + ch0 + ct * CT) * 50;
        const float* __restrict__ IS = sm + OFF_ISF + pt * 6;   // row step 92

        u64 acc[CT][3];
#pragma unroll
        for (int i = 0; i < CT; i++)
#pragma unroll
            for (int j = 0; j < 3; j++) acc[i][j] = 0ull;

#pragma unroll 3
        for (int k = 0; k < 45; k++) {
            u64 iv[3];
#pragma unroll
            for (int j = 0; j < 3; j++)
                iv[j] = *reinterpret_cast<const u64*>(IS + k * 92 + 2 * j);
#pragma unroll
            for (int i = 0; i < CT; i++) {
                u64 xp = pack2(T[i * 50 + k]);
#pragma unroll
                for (int j = 0; j < 3; j++) acc[i][j] = fma2(xp, iv[j], acc[i][j]);
            }
        }

        float* __restrict__ S = sm + OFF_SIG + (bi * 32 + ct * CT) * 92 + pt * 6;
#pragma unroll
        for (int i = 0; i < CT; i++)
#pragma unroll
            for (int j = 0; j < 3; j++) {
                float2 r = unpack2(acc[i][j]);
                r.x = fmaxf(r.x, 0.f);
                r.y = fmaxf(r.y, 0.f);
                *reinterpret_cast<float2*>(S + i * 92 + 2 * j) = r;
            }
    }
}

// GEMM2 (f32x2): x[bi][c][k0..k0+5] = sum_p sig[bi][c][p] * sft[p][k]
// tiles: 8 k-tiles of 6 (3 pairs; k=45..47 padded zero) x CT channels
template <int NCH, int CT>
__device__ __forceinline__ void gemm2_step(float* sm, int ch0, int tid)
{
    constexpr int SLOTS = 2 * (NCH / CT) * 8;
    if (tid < SLOTS) {
        const int kt = tid % 8;
        const int bi = (tid / 8) & 1;
        const int ct = tid / 16;
        const int k0 = kt * 6;
        const float* __restrict__ S = sm + OFF_SIG + (bi * 32 + ct * CT) * 92;
        const float* __restrict__ F = sm + OFF_SFT + k0;        // row step 48

        u64 acc[CT][3];
#pragma unroll
        for (int i = 0; i < CT; i++)
#pragma unroll
            for (int j = 0; j < 3; j++) acc[i][j] = 0ull;

#pragma unroll 3
        for (int p = 0; p < 90; p++) {
            u64 fv[3];
#pragma unroll
            for (int j = 0; j < 3; j++)
                fv[j] = *reinterpret_cast<const u64*>(F + p * 48 + 2 * j);
#pragma unroll
            for (int i = 0; i < CT; i++) {
                u64 sp = pack2(S[i * 92 + p]);
#pragma unroll
                for (int j = 0; j < 3; j++) acc[i][j] = fma2(sp, fv[j], acc[i][j]);
            }
        }

        float* __restrict__ A = sm + OFF_A + (bi * 64 + ch0 + ct * CT) * 50 + k0;
#pragma unroll
        for (int i = 0; i < CT; i++)
#pragma unroll
            for (int j = 0; j < 3; j++)
                *reinterpret_cast<float2*>(A + i * 50 + 2 * j) = unpack2(acc[i][j]);
    }
}

template <int Cin, int Cout, int WOFF, int RS, int CT1, int CT2>
__device__ __forceinline__ void run_layer(float* sm, int tid)
{
    sconv_step<Cin, Cout, WOFF, RS>(sm, tid);
    __syncthreads();
    constexpr int CH = (Cout < 32) ? Cout : 32;
#pragma unroll
    for (int ch0 = 0; ch0 < Cout; ch0 += 32) {
        gemm1_step<CH, CT1>(sm, ch0, tid);
        __syncthreads();
        gemm2_step<CH, CT2>(sm, ch0, tid);
        __syncthreads();
    }
}

__device__ __forceinline__ void stage_w(float* dst, const float* __restrict__ g,
                                        int Cout, int Cin, int rs, int tid)
{
    const int row = Cin * 5;
    const int n = Cout * row;
    for (int i = tid; i < n; i += NT) {
        int o = i / row;
        int r = i - o * row;
        dst[o * rs + r] = g[i];
    }
}

extern "C" __global__ void __launch_bounds__(NT, 1)
scnn_kernel(const float* __restrict__ x, const float* __restrict__ sft,
            const float* __restrict__ isft,
            const float* __restrict__ w1, const float* __restrict__ w2,
            const float* __restrict__ w3, const float* __restrict__ w4,
            const float* __restrict__ w5, const float* __restrict__ w6,
            float* __restrict__ out)
{
    extern __shared__ float sm[];
    const int tid = threadIdx.x;

    // ---- stage static operands (transposed for pair loads) ----
    for (int i = tid; i < 90 * 48; i += NT) {              // SFT[p][k], zero k>=45
        int p = i / 48, k = i - p * 48;
        sm[OFF_SFT + i] = (k < 45) ? sft[k * 90 + p] : 0.f;
    }
    for (int i = tid; i < 45 * 92; i += NT) {              // ISF[k][p]
        int k = i / 92, p = i - k * 92;
        sm[OFF_ISF + i] = (p < 90) ? isft[p * 45 + k] : 0.f;
    }
    if (tid < 45) {
        int k = tid;
        int d = (k >= 28) ? 4 : (k >= 15) ? 3 : (k >= 6) ? 2 : (k >= 1) ? 1 : 0;
        sm[OFF_SC + k] = sqrtf(3.14159265358979323846f / (float)(4 * d + 1));
    }
    stage_w(sm + OFF_W + WOFF1, w1, 16, 4, 21, tid);
    stage_w(sm + OFF_W + WOFF2, w2, 32, 16, 81, tid);
    stage_w(sm + OFF_W + WOFF3, w3, 64, 32, 161, tid);
    stage_w(sm + OFF_W + WOFF4, w4, 32, 64, 321, tid);
    stage_w(sm + OFF_W + WOFF5, w5, 16, 32, 161, tid);
    stage_w(sm + OFF_W + WOFF6, w6, 4, 16, 81, tid);
    __syncthreads();

    // ---- persistent stride loop over batch pairs ----
    for (int pair = blockIdx.x; pair < NPAIR; pair += gridDim.x) {
        const int b0 = pair * 2;

        // load x for 2 batch elements into [2][4][50] (pad cols zeroed)
        for (int i = tid; i < 400; i += NT) {
            int bi = i / 200, r = i - bi * 200;
            int c = r / 50, k = r - c * 50;
            int b = b0 + bi;
            float v = 0.f;
            if (k < 45 && b < BATCH) v = x[b * 180 + c * 45 + k];
            sm[OFF_A + (bi * 64 + c) * 50 + k] = v;
        }
        __syncthreads();

        run_layer<4,  16, WOFF1, 21,  2, 2>(sm, tid);
        run_layer<16, 32, WOFF2, 81,  2, 2>(sm, tid);
        run_layer<32, 64, WOFF3, 161, 2, 2>(sm, tid);
        run_layer<64, 32, WOFF4, 321, 2, 2>(sm, tid);
        run_layer<32, 16, WOFF5, 161, 2, 2>(sm, tid);
        run_layer<16, 4,  WOFF6, 81,  1, 1>(sm, tid);

        // store output: [2][4][45]
        for (int i = tid; i < 360; i += NT) {
            int bi = i / 180, r = i - bi * 180;
            int c = r / 45, k = r - c * 45;
            int b = b0 + bi;
            if (b < BATCH) out[b * 180 + r] = sm[OFF_A + (bi * 64 + c) * 50 + k];
        }
        __syncthreads();   // protect bufA before next iteration's load
    }
}

extern "C" void kernel_launch(void* const* d_in, const int* in_sizes, int n_in,
                              void* d_out, int out_size)
{
    cudaFuncSetAttribute(scnn_kernel, cudaFuncAttributeMaxDynamicSharedMemorySize,
                         SMEM_BYTES);
    scnn_kernel<<<NBLK, NT, SMEM_BYTES>>>(
        (const float*)d_in[0], (const float*)d_in[1], (const float*)d_in[2],
        (const float*)d_in[3], (const float*)d_in[4], (const float*)d_in[5],
        (const float*)d_in[6], (const float*)d_in[7], (const float*)d_in[8],
        (float*)d_out);
}

// round 4
// speedup vs baseline: 1.0651x; 1.0651x over previous
#include <cuda_runtime.h>
#include <math.h>

#define NT    512
#define NBLK  592
#define BATCH 50000
#define BT    4
#define NQUAD (BATCH / BT)

typedef unsigned long long u64;

// ---- shared memory layout (float offsets) ----
#define OFF_SFT  0            // SFT[p][k]: 90 x 48 (k>=45 zero)
#define OFF_ISF  4320         // ISF[k][p]: 45 x 92 (p>=90 zero)
#define OFF_SC   8460         // scale[45] (pad 48)
#define OFF_A    8508         // x buffer  [4][64][48]
#define OFF_B    20796        // t buffer  [4][64][48]
#define OFF_SIG  33084        // sig       [4][32][92]
#define SMEM_FLOATS 44860
#define SMEM_BYTES  (SMEM_FLOATS * 4)

static_assert(OFF_SIG + 4 * 32 * 92 == SMEM_FLOATS, "smem layout");

// packed fp32x2 helpers
__device__ __forceinline__ u64 fma2(u64 a, u64 b, u64 c) {
    u64 d;
    asm("fma.rn.f32x2 %0, %1, %2, %3;" : "=l"(d) : "l"(a), "l"(b), "l"(c));
    return d;
}
__device__ __forceinline__ u64 pack2(float v) {
    u64 d;
    asm("mov.b64 %0, {%1, %1};" : "=l"(d) : "f"(v));
    return d;
}
__device__ __forceinline__ float2 unpack2(u64 v) {
    float2 r;
    asm("mov.b64 {%0, %1}, %2;" : "=f"(r.x), "=f"(r.y) : "l"(v));
    return r;
}

// sconv k-tiles aligned to degree-group boundaries (single ls_idx per tile)
__constant__ int c_tk0[15] = {0, 1, 5, 6, 10, 14, 15, 19, 23, 27, 28, 32, 36, 40, 44};
__constant__ int c_tkl[15] = {1, 4, 1, 4, 4, 1, 4, 4, 4, 1, 4, 4, 4, 4, 1};
__constant__ int c_td[15]  = {0, 1, 1, 2, 2, 2, 3, 3, 3, 3, 4, 4, 4, 4, 4};

// sconv: t[bi][o][k] = scale[k] * sum_c x[bi][c][k] * W[o][c][d(k)]
// weights read from GLOBAL (L1/L2 cached, heavy warp dedup)
template <int Cin, int Cout, int OT>
__device__ __forceinline__ void sconv_step(float* sm, const float* __restrict__ gw, int tid)
{
    constexpr int SLOTS = BT * (Cout / OT) * 15;
    if (tid < SLOTS) {
        const int kt = tid % 15;
        const int bi = (tid / 15) & 3;
        const int ot = tid / (15 * BT);
        const int k0   = c_tk0[kt];
        const int klen = c_tkl[kt];
        const int d    = c_td[kt];
        const float* __restrict__ A = sm + OFF_A + (bi * 64) * 48 + k0;
        const float* __restrict__ W = gw + (ot * OT) * (Cin * 5) + d;

        float acc[OT][4];
#pragma unroll
        for (int i = 0; i < OT; i++)
#pragma unroll
            for (int j = 0; j < 4; j++) acc[i][j] = 0.f;

#pragma unroll 4
        for (int c = 0; c < Cin; c++) {
            float xv[4];
#pragma unroll
            for (int j = 0; j < 4; j++) xv[j] = A[c * 48 + j];   // k0+3 <= 47 safe
#pragma unroll
            for (int i = 0; i < OT; i++) {
                float w = __ldg(W + i * (Cin * 5) + c * 5);
#pragma unroll
                for (int j = 0; j < 4; j++) acc[i][j] = fmaf(w, xv[j], acc[i][j]);
            }
        }

        float* __restrict__ B = sm + OFF_B + (bi * 64 + ot * OT) * 48 + k0;
#pragma unroll
        for (int i = 0; i < OT; i++)
#pragma unroll
            for (int j = 0; j < 4; j++)
                if (j < klen) B[i * 48 + j] = acc[i][j] * sm[OFF_SC + k0 + j];
    }
}

// GEMM1 (f32x2): sig[bi][c][p0..p0+5] = relu( sum_k t[bi][c][k] * ISF[k][p] )
// 15 p-tiles of 6 x CT=4 channels; stream ISF rows (24B, conflict-free spread)
template <int NCH>
__device__ __forceinline__ void gemm1_step(float* sm, int ch0, int tid)
{
    constexpr int SLOTS = BT * (NCH / 4) * 15;
    if (tid < SLOTS) {
        const int pt = tid % 15;
        const int bi = (tid / 15) & 3;
        const int ct = tid / (15 * BT);
        const float* __restrict__ T  = sm + OFF_B + (bi * 64 + ch0 + ct * 4) * 48;
        const float* __restrict__ IS = sm + OFF_ISF + pt * 6;   // row step 92

        u64 acc[4][3];
#pragma unroll
        for (int i = 0; i < 4; i++)
#pragma unroll
            for (int j = 0; j < 3; j++) acc[i][j] = 0ull;

#pragma unroll 3
        for (int k = 0; k < 45; k++) {
            u64 iv[3];
#pragma unroll
            for (int j = 0; j < 3; j++)
                iv[j] = *reinterpret_cast<const u64*>(IS + k * 92 + 2 * j);
#pragma unroll
            for (int i = 0; i < 4; i++) {
                u64 xp = pack2(T[i * 48 + k]);
#pragma unroll
                for (int j = 0; j < 3; j++) acc[i][j] = fma2(xp, iv[j], acc[i][j]);
            }
        }

        float* __restrict__ S = sm + OFF_SIG + (bi * 32 + ct * 4) * 92 + pt * 6;
#pragma unroll
        for (int i = 0; i < 4; i++)
#pragma unroll
            for (int j = 0; j < 3; j++) {
                float2 r = unpack2(acc[i][j]);
                r.x = fmaxf(r.x, 0.f);
                r.y = fmaxf(r.y, 0.f);
                *reinterpret_cast<float2*>(S + i * 92 + 2 * j) = r;
            }
    }
}

// GEMM2 (f32x2): x[bi][c][k0..k0+5] = sum_p sig[bi][c][p] * SFT[p][k]
// 8 k-tiles of 6 (k=45..47 zero-padded) x CT=4 channels
template <int NCH>
__device__ __forceinline__ void gemm2_step(float* sm, int ch0, int tid)
{
    constexpr int SLOTS = BT * (NCH / 4) * 8;
    if (tid < SLOTS) {
        const int kt = tid % 8;
        const int bi = (tid / 8) & 3;
        const int ct = tid / (8 * BT);
        const int k0 = kt * 6;
        const float* __restrict__ S = sm + OFF_SIG + (bi * 32 + ct * 4) * 92;
        const float* __restrict__ F = sm + OFF_SFT + k0;        // row step 48

        u64 acc[4][3];
#pragma unroll
        for (int i = 0; i < 4; i++)
#pragma unroll
            for (int j = 0; j < 3; j++) acc[i][j] = 0ull;

#pragma unroll 3
        for (int p = 0; p < 90; p++) {
            u64 fv[3];
#pragma unroll
            for (int j = 0; j < 3; j++)
                fv[j] = *reinterpret_cast<const u64*>(F + p * 48 + 2 * j);
#pragma unroll
            for (int i = 0; i < 4; i++) {
                u64 sp = pack2(S[i * 92 + p]);
#pragma unroll
                for (int j = 0; j < 3; j++) acc[i][j] = fma2(sp, fv[j], acc[i][j]);
            }
        }

        float* __restrict__ A = sm + OFF_A + (bi * 64 + ch0 + ct * 4) * 48 + k0;
#pragma unroll
        for (int i = 0; i < 4; i++)
#pragma unroll
            for (int j = 0; j < 3; j++)
                *reinterpret_cast<float2*>(A + i * 48 + 2 * j) = unpack2(acc[i][j]);
    }
}

template <int Cin, int Cout, int OT>
__device__ __forceinline__ void run_layer(float* sm, const float* __restrict__ gw, int tid)
{
    sconv_step<Cin, Cout, OT>(sm, gw, tid);
    __syncthreads();
    constexpr int CH = (Cout < 32) ? Cout : 32;
#pragma unroll
    for (int ch0 = 0; ch0 < Cout; ch0 += 32) {
        gemm1_step<CH>(sm, ch0, tid);
        __syncthreads();
        gemm2_step<CH>(sm, ch0, tid);
        __syncthreads();
    }
}

extern "C" __global__ void __launch_bounds__(NT, 1)
scnn_kernel(const float* __restrict__ x, const float* __restrict__ sft,
            const float* __restrict__ isft,
            const float* __restrict__ w1, const float* __restrict__ w2,
            const float* __restrict__ w3, const float* __restrict__ w4,
            const float* __restrict__ w5, const float* __restrict__ w6,
            float* __restrict__ out)
{
    extern __shared__ float sm[];
    const int tid = threadIdx.x;

    // ---- stage SFT/ISF transposed (+zero pads) ----
    for (int i = tid; i < 90 * 48; i += NT) {          // SFT[p][k], zero k>=45
        int p = i / 48, k = i - p * 48;
        sm[OFF_SFT + i] = (k < 45) ? sft[k * 90 + p] : 0.f;
    }
    for (int i = tid; i < 45 * 92; i += NT) {          // ISF[k][p], zero p>=90
        int k = i / 92, p = i - k * 92;
        sm[OFF_ISF + i] = (p < 90) ? isft[p * 45 + k] : 0.f;
    }
    if (tid < 45) {
        int k = tid;
        int d = (k >= 28) ? 4 : (k >= 15) ? 3 : (k >= 6) ? 2 : (k >= 1) ? 1 : 0;
        sm[OFF_SC + k] = sqrtf(3.14159265358979323846f / (float)(4 * d + 1));
    }
    __syncthreads();

    // ---- persistent stride loop over batch quads ----
    for (int quad = blockIdx.x; quad < NQUAD; quad += gridDim.x) {
        const int b0 = quad * BT;

        // load x for 4 batch elements into [4][4][48]
        for (int i = tid; i < BT * 4 * 48; i += NT) {
            int bi = i / 192, r = i - bi * 192;
            int c = r / 48, k = r - c * 48;
            float v = 0.f;
            if (k < 45) v = x[(b0 + bi) * 180 + c * 45 + k];
            sm[OFF_A + (bi * 64 + c) * 48 + k] = v;
        }
        __syncthreads();

        run_layer<4,  16, 2>(sm, w1, tid);
        run_layer<16, 32, 4>(sm, w2, tid);
        run_layer<32, 64, 8>(sm, w3, tid);
        run_layer<64, 32, 4>(sm, w4, tid);
        run_layer<32, 16, 2>(sm, w5, tid);
        run_layer<16, 4,  1>(sm, w6, tid);

        // store output: [4][4][45]
        for (int i = tid; i < BT * 180; i += NT) {
            int bi = i / 180, r = i - bi * 180;
            int c = r / 45, k = r - c * 45;
            out[(b0 + bi) * 180 + r] = sm[OFF_A + (bi * 64 + c) * 48 + k];
        }
        __syncthreads();   // protect bufA before next iteration's load
    }
}

extern "C" void kernel_launch(void* const* d_in, const int* in_sizes, int n_in,
                              void* d_out, int out_size)
{
    cudaFuncSetAttribute(scnn_kernel, cudaFuncAttributeMaxDynamicSharedMemorySize,
                         SMEM_BYTES);
    scnn_kernel<<<NBLK, NT, SMEM_BYTES>>>(
        (const float*)d_in[0], (const float*)d_in[1], (const float*)d_in[2],
        (const float*)d_in[3], (const float*)d_in[4], (const float*)d_in[5],
        (const float*)d_in[6], (const float*)d_in[7], (const float*)d_in[8],
        (float*)d_out);
}

// round 6
// speedup vs baseline: 1.6236x; 1.5244x over previous
#include <cuda_runtime.h>
#include <math.h>

#define NT    512
#define NBLK  592
#define BATCH 50000
#define BT    4
#define NQUAD (BATCH / BT)

typedef unsigned long long u64;

// ---- shared memory layout (float offsets) ----
// Interleaved rows: row = ch*4 + bi. EVEN strides (float2-aligned) chosen so
// bi-deltas 1..3 map to distinct banks: 50 -> {18,4,22}, 94 -> {30,28,26}.
#define OFF_SFT  0            // SFT[p][k]: 90 x 48 (k>=45 zero)
#define OFF_ISF  4320         // ISF[k][p]: 45 x 92 (p>=90 zero)
#define OFF_SC   8460         // scale[45] (pad 48)
#define OFF_A    8508         // x buffer  [256 rows][50]  row = ch*4+bi, ch<64
#define OFF_B    21308        // t buffer  [256 rows][50]
#define OFF_SIG  34108        // sig       [128 rows][94]  row = ch*4+bi, ch<32
#define SMEM_FLOATS 46140
#define SMEM_BYTES  (SMEM_FLOATS * 4)

static_assert(OFF_SIG + 128 * 94 == SMEM_FLOATS, "smem layout");
static_assert((OFF_A & 1) == 0 && (OFF_B & 1) == 0 && (OFF_SIG & 1) == 0, "align");

// packed fp32x2 helpers
__device__ __forceinline__ u64 fma2(u64 a, u64 b, u64 c) {
    u64 d;
    asm("fma.rn.f32x2 %0, %1, %2, %3;" : "=l"(d) : "l"(a), "l"(b), "l"(c));
    return d;
}
__device__ __forceinline__ u64 pack2(float v) {
    u64 d;
    asm("mov.b64 %0, {%1, %1};" : "=l"(d) : "f"(v));
    return d;
}
__device__ __forceinline__ float2 unpack2(u64 v) {
    float2 r;
    asm("mov.b64 {%0, %1}, %2;" : "=f"(r.x), "=f"(r.y) : "l"(v));
    return r;
}

// sconv k-tiles aligned to degree-group boundaries (single ls_idx per tile)
__constant__ int c_tk0[15] = {0, 1, 5, 6, 10, 14, 15, 19, 23, 27, 28, 32, 36, 40, 44};
__constant__ int c_tkl[15] = {1, 4, 1, 4, 4, 1, 4, 4, 4, 1, 4, 4, 4, 4, 1};
__constant__ int c_td[15]  = {0, 1, 1, 2, 2, 2, 3, 3, 3, 3, 4, 4, 4, 4, 4};

// sconv: t[bi][o][k] = scale[k] * sum_c x[bi][c][k] * W[o][c][d(k)]
template <int Cin, int Cout, int OT>
__device__ __forceinline__ void sconv_step(float* sm, const float* __restrict__ gw, int tid)
{
    constexpr int SLOTS = BT * (Cout / OT) * 15;
    if (tid < SLOTS) {
        const int kt = tid % 15;
        const int bi = (tid / 15) & 3;
        const int ot = tid / (15 * BT);
        const int k0   = c_tk0[kt];
        const int klen = c_tkl[kt];
        const int d    = c_td[kt];
        const float* __restrict__ A = sm + OFF_A + bi * 50 + k0;      // +c*200
        const float* __restrict__ W = gw + (ot * OT) * (Cin * 5) + d;

        float acc[OT][4];
#pragma unroll
        for (int i = 0; i < OT; i++)
#pragma unroll
            for (int j = 0; j < 4; j++) acc[i][j] = 0.f;

#pragma unroll 4
        for (int c = 0; c < Cin; c++) {
            float xv[4];
#pragma unroll
            for (int j = 0; j < 4; j++) xv[j] = A[c * 200 + j];   // k0+3 <= 47 safe
#pragma unroll
            for (int i = 0; i < OT; i++) {
                float w = __ldg(W + i * (Cin * 5) + c * 5);
#pragma unroll
                for (int j = 0; j < 4; j++) acc[i][j] = fmaf(w, xv[j], acc[i][j]);
            }
        }

        float* __restrict__ B = sm + OFF_B + ((ot * OT) * 4 + bi) * 50 + k0;
#pragma unroll
        for (int i = 0; i < OT; i++)
#pragma unroll
            for (int j = 0; j < 4; j++)
                if (j < klen) B[i * 200 + j] = acc[i][j] * sm[OFF_SC + k0 + j];
    }
}

// GEMM1 (f32x2): sig[row][p0..p0+5] = relu( sum_k t[row][k] * ISF[k][p] )
template <int NCH>
__device__ __forceinline__ void gemm1_step(float* sm, int ch0, int tid)
{
    constexpr int SLOTS = BT * (NCH / 4) * 15;
    if (tid < SLOTS) {
        const int pt = tid % 15;
        const int bi = (tid / 15) & 3;
        const int ct = tid / (15 * BT);
        const float* __restrict__ T  = sm + OFF_B + ((ch0 + ct * 4) * 4 + bi) * 50;
        const float* __restrict__ IS = sm + OFF_ISF + pt * 6;   // row step 92

        u64 acc[4][3];
#pragma unroll
        for (int i = 0; i < 4; i++)
#pragma unroll
            for (int j = 0; j < 3; j++) acc[i][j] = 0ull;

#pragma unroll 3
        for (int k = 0; k < 45; k++) {
            u64 iv[3];
#pragma unroll
            for (int j = 0; j < 3; j++)
                iv[j] = *reinterpret_cast<const u64*>(IS + k * 92 + 2 * j);
#pragma unroll
            for (int i = 0; i < 4; i++) {
                u64 xp = pack2(T[i * 200 + k]);
#pragma unroll
                for (int j = 0; j < 3; j++) acc[i][j] = fma2(xp, iv[j], acc[i][j]);
            }
        }

        float* __restrict__ S = sm + OFF_SIG + ((ct * 4) * 4 + bi) * 94 + pt * 6;
#pragma unroll
        for (int i = 0; i < 4; i++)
#pragma unroll
            for (int j = 0; j < 3; j++) {
                float2 r = unpack2(acc[i][j]);
                r.x = fmaxf(r.x, 0.f);
                r.y = fmaxf(r.y, 0.f);
                *reinterpret_cast<float2*>(S + i * 376 + 2 * j) = r;   // 4*94
            }
    }
}

// GEMM2 (f32x2): x[row][k0..k0+5] = sum_p sig[row][p] * SFT[p][k]
template <int NCH>
__device__ __forceinline__ void gemm2_step(float* sm, int ch0, int tid)
{
    constexpr int SLOTS = BT * (NCH / 4) * 8;
    if (tid < SLOTS) {
        const int kt = tid % 8;
        const int bi = (tid / 8) & 3;
        const int ct = tid / (8 * BT);
        const int k0 = kt * 6;
        const float* __restrict__ S = sm + OFF_SIG + ((ct * 4) * 4 + bi) * 94;
        const float* __restrict__ F = sm + OFF_SFT + k0;        // row step 48

        u64 acc[4][3];
#pragma unroll
        for (int i = 0; i < 4; i++)
#pragma unroll
            for (int j = 0; j < 3; j++) acc[i][j] = 0ull;

#pragma unroll 3
        for (int p = 0; p < 90; p++) {
            u64 fv[3];
#pragma unroll
            for (int j = 0; j < 3; j++)
                fv[j] = *reinterpret_cast<const u64*>(F + p * 48 + 2 * j);
#pragma unroll
            for (int i = 0; i < 4; i++) {
                u64 sp = pack2(S[i * 376 + p]);                  // 4*94
#pragma unroll
                for (int j = 0; j < 3; j++) acc[i][j] = fma2(sp, fv[j], acc[i][j]);
            }
        }

        float* __restrict__ A = sm + OFF_A + ((ch0 + ct * 4) * 4 + bi) * 50 + k0;
#pragma unroll
        for (int i = 0; i < 4; i++)
#pragma unroll
            for (int j = 0; j < 3; j++)
                *reinterpret_cast<float2*>(A + i * 200 + 2 * j) = unpack2(acc[i][j]);
    }
}

template <int Cin, int Cout, int OT>
__device__ __forceinline__ void run_layer(float* sm, const float* __restrict__ gw, int tid)
{
    sconv_step<Cin, Cout, OT>(sm, gw, tid);
    __syncthreads();
    constexpr int CH = (Cout < 32) ? Cout : 32;
#pragma unroll
    for (int ch0 = 0; ch0 < Cout; ch0 += 32) {
        gemm1_step<CH>(sm, ch0, tid);
        __syncthreads();
        gemm2_step<CH>(sm, ch0, tid);
        __syncthreads();
    }
}

extern "C" __global__ void __launch_bounds__(NT, 1)
scnn_kernel(const float* __restrict__ x, const float* __restrict__ sft,
            const float* __restrict__ isft,
            const float* __restrict__ w1, const float* __restrict__ w2,
            const float* __restrict__ w3, const float* __restrict__ w4,
            const float* __restrict__ w5, const float* __restrict__ w6,
            float* __restrict__ out)
{
    extern __shared__ float sm[];
    const int tid = threadIdx.x;

    // ---- stage SFT/ISF transposed (+zero pads) ----
    for (int i = tid; i < 90 * 48; i += NT) {          // SFT[p][k], zero k>=45
        int p = i / 48, k = i - p * 48;
        sm[OFF_SFT + i] = (k < 45) ? sft[k * 90 + p] : 0.f;
    }
    for (int i = tid; i < 45 * 92; i += NT) {          // ISF[k][p], zero p>=90
        int k = i / 92, p = i - k * 92;
        sm[OFF_ISF + i] = (p < 90) ? isft[p * 45 + k] : 0.f;
    }
    if (tid < 45) {
        int k = tid;
        int d = (k >= 28) ? 4 : (k >= 15) ? 3 : (k >= 6) ? 2 : (k >= 1) ? 1 : 0;
        sm[OFF_SC + k] = sqrtf(3.14159265358979323846f / (float)(4 * d + 1));
    }
    __syncthreads();

    // ---- persistent stride loop over batch quads ----
    for (int quad = blockIdx.x; quad < NQUAD; quad += gridDim.x) {
        const int b0 = quad * BT;

        // load x: interleaved rows [c*4+bi][50]
        for (int i = tid; i < BT * 4 * 48; i += NT) {
            int bi = i / 192, r = i - bi * 192;
            int c = r / 48, k = r - c * 48;
            float v = 0.f;
            if (k < 45) v = x[(b0 + bi) * 180 + c * 45 + k];
            sm[OFF_A + (c * 4 + bi) * 50 + k] = v;
        }
        __syncthreads();

        run_layer<4,  16, 2>(sm, w1, tid);
        run_layer<16, 32, 4>(sm, w2, tid);
        run_layer<32, 64, 8>(sm, w3, tid);
        run_layer<64, 32, 4>(sm, w4, tid);
        run_layer<32, 16, 2>(sm, w5, tid);
        run_layer<16, 4,  1>(sm, w6, tid);

        // store output
        for (int i = tid; i < BT * 180; i += NT) {
            int bi = i / 180, r = i - bi * 180;
            int c = r / 45, k = r - c * 45;
            out[(b0 + bi) * 180 + r] = sm[OFF_A + (c * 4 + bi) * 50 + k];
        }
        __syncthreads();   // protect bufA before next iteration's load
    }
}

extern "C" void kernel_launch(void* const* d_in, const int* in_sizes, int n_in,
                              void* d_out, int out_size)
{
    cudaFuncSetAttribute(scnn_kernel, cudaFuncAttributeMaxDynamicSharedMemorySize,
                         SMEM_BYTES);
    scnn_kernel<<<NBLK, NT, SMEM_BYTES>>>(
        (const float*)d_in[0], (const float*)d_in[1], (const float*)d_in[2],
        (const float*)d_in[3], (const float*)d_in[4], (const float*)d_in[5],
        (const float*)d_in[6], (const float*)d_in[7], (const float*)d_in[8],
        (float*)d_out);
}

// round 7
// speedup vs baseline: 1.6243x; 1.0004x over previous
#include <cuda_runtime.h>
#include <math.h>

#define NT    512
#define NBLK  592
#define BATCH 50000
#define BT    4
#define NQUAD (BATCH / BT)

typedef unsigned long long u64;

// ---- shared memory layout (float offsets) ----
// Interleaved rows: row = ch*4 + bi. EVEN strides (float2-aligned) chosen so
// bi-deltas 1..3 map to distinct banks: 50 -> {18,4,22}, 94 -> {30,28,26}.
#define OFF_SFT  0            // SFT[p][k]: 90 x 48 (k>=45 zero)
#define OFF_ISF  4320         // ISF[k][p]: 45 x 92 (p>=90 zero)
#define OFF_SC   8460         // scale[45] (pad 48)
#define OFF_A    8508         // x buffer  [256 rows][50]  row = ch*4+bi, ch<64
#define OFF_B    21308        // t buffer  [256 rows][50]
#define OFF_SIG  34108        // sig       [128 rows][94]  row = ch*4+bi, ch<32
#define SMEM_FLOATS 46140
#define SMEM_BYTES  (SMEM_FLOATS * 4)

static_assert(OFF_SIG + 128 * 94 == SMEM_FLOATS, "smem layout");
static_assert((OFF_A & 1) == 0 && (OFF_B & 1) == 0 && (OFF_SIG & 1) == 0, "align");

// packed fp32x2 helpers
__device__ __forceinline__ u64 fma2(u64 a, u64 b, u64 c) {
    u64 d;
    asm("fma.rn.f32x2 %0, %1, %2, %3;" : "=l"(d) : "l"(a), "l"(b), "l"(c));
    return d;
}
__device__ __forceinline__ u64 pack2(float v) {
    u64 d;
    asm("mov.b64 %0, {%1, %1};" : "=l"(d) : "f"(v));
    return d;
}
__device__ __forceinline__ float2 unpack2(u64 v) {
    float2 r;
    asm("mov.b64 {%0, %1}, %2;" : "=f"(r.x), "=f"(r.y) : "l"(v));
    return r;
}

// sconv k-tiles aligned to degree-group boundaries (single ls_idx per tile)
__constant__ int c_tk0[15] = {0, 1, 5, 6, 10, 14, 15, 19, 23, 27, 28, 32, 36, 40, 44};
__constant__ int c_tkl[15] = {1, 4, 1, 4, 4, 1, 4, 4, 4, 1, 4, 4, 4, 4, 1};
__constant__ int c_td[15]  = {0, 1, 1, 2, 2, 2, 3, 3, 3, 3, 4, 4, 4, 4, 4};

// sconv: t[bi][o][k] = scale[k] * sum_c x[bi][c][k] * W[o][c][d(k)]
template <int Cin, int Cout, int OT>
__device__ __forceinline__ void sconv_step(float* sm, const float* __restrict__ gw, int tid)
{
    constexpr int SLOTS = BT * (Cout / OT) * 15;
    if (tid < SLOTS) {
        const int kt = tid % 15;
        const int bi = (tid / 15) & 3;
        const int ot = tid / (15 * BT);
        const int k0   = c_tk0[kt];
        const int klen = c_tkl[kt];
        const int d    = c_td[kt];
        const float* __restrict__ A = sm + OFF_A + bi * 50 + k0;      // +c*200
        const float* __restrict__ W = gw + (ot * OT) * (Cin * 5) + d;

        float acc[OT][4];
#pragma unroll
        for (int i = 0; i < OT; i++)
#pragma unroll
            for (int j = 0; j < 4; j++) acc[i][j] = 0.f;

#pragma unroll 4
        for (int c = 0; c < Cin; c++) {
            float xv[4];
#pragma unroll
            for (int j = 0; j < 4; j++) xv[j] = A[c * 200 + j];   // k0+3 <= 47 safe
#pragma unroll
            for (int i = 0; i < OT; i++) {
                float w = __ldg(W + i * (Cin * 5) + c * 5);
#pragma unroll
                for (int j = 0; j < 4; j++) acc[i][j] = fmaf(w, xv[j], acc[i][j]);
            }
        }

        float* __restrict__ B = sm + OFF_B + ((ot * OT) * 4 + bi) * 50 + k0;
#pragma unroll
        for (int i = 0; i < OT; i++)
#pragma unroll
            for (int j = 0; j < 4; j++)
                if (j < klen) B[i * 200 + j] = acc[i][j] * sm[OFF_SC + k0 + j];
    }
}

// GEMM1 (f32x2): sig[row][p0..p0+5] = relu( sum_k t[row][k] * ISF[k][p] )
template <int NCH>
__device__ __forceinline__ void gemm1_step(float* sm, int ch0, int tid)
{
    constexpr int SLOTS = BT * (NCH / 4) * 15;
    if (tid < SLOTS) {
        const int pt = tid % 15;
        const int bi = (tid / 15) & 3;
        const int ct = tid / (15 * BT);
        const float* __restrict__ T  = sm + OFF_B + ((ch0 + ct * 4) * 4 + bi) * 50;
        const float* __restrict__ IS = sm + OFF_ISF + pt * 6;   // row step 92

        u64 acc[4][3];
#pragma unroll
        for (int i = 0; i < 4; i++)
#pragma unroll
            for (int j = 0; j < 3; j++) acc[i][j] = 0ull;

#pragma unroll 3
        for (int k = 0; k < 45; k++) {
            u64 iv[3];
#pragma unroll
            for (int j = 0; j < 3; j++)
                iv[j] = *reinterpret_cast<const u64*>(IS + k * 92 + 2 * j);
#pragma unroll
            for (int i = 0; i < 4; i++) {
                u64 xp = pack2(T[i * 200 + k]);
#pragma unroll
                for (int j = 0; j < 3; j++) acc[i][j] = fma2(xp, iv[j], acc[i][j]);
            }
        }

        float* __restrict__ S = sm + OFF_SIG + ((ct * 4) * 4 + bi) * 94 + pt * 6;
#pragma unroll
        for (int i = 0; i < 4; i++)
#pragma unroll
            for (int j = 0; j < 3; j++) {
                float2 r = unpack2(acc[i][j]);
                r.x = fmaxf(r.x, 0.f);
                r.y = fmaxf(r.y, 0.f);
                *reinterpret_cast<float2*>(S + i * 376 + 2 * j) = r;   // 4*94
            }
    }
}

// GEMM2 (f32x2): x[row][k0..k0+5] = sum_p sig[row][p] * SFT[p][k]
template <int NCH>
__device__ __forceinline__ void gemm2_step(float* sm, int ch0, int tid)
{
    constexpr int SLOTS = BT * (NCH / 4) * 8;
    if (tid < SLOTS) {
        const int kt = tid % 8;
        const int bi = (tid / 8) & 3;
        const int ct = tid / (8 * BT);
        const int k0 = kt * 6;
        const float* __restrict__ S = sm + OFF_SIG + ((ct * 4) * 4 + bi) * 94;
        const float* __restrict__ F = sm + OFF_SFT + k0;        // row step 48

        u64 acc[4][3];
#pragma unroll
        for (int i = 0; i < 4; i++)
#pragma unroll
            for (int j = 0; j < 3; j++) acc[i][j] = 0ull;

#pragma unroll 3
        for (int p = 0; p < 90; p++) {
            u64 fv[3];
#pragma unroll
            for (int j = 0; j < 3; j++)
                fv[j] = *reinterpret_cast<const u64*>(F + p * 48 + 2 * j);
#pragma unroll
            for (int i = 0; i < 4; i++) {
                u64 sp = pack2(S[i * 376 + p]);                  // 4*94
#pragma unroll
                for (int j = 0; j < 3; j++) acc[i][j] = fma2(sp, fv[j], acc[i][j]);
            }
        }

        float* __restrict__ A = sm + OFF_A + ((ch0 + ct * 4) * 4 + bi) * 50 + k0;
#pragma unroll
        for (int i = 0; i < 4; i++)
#pragma unroll
            for (int j = 0; j < 3; j++)
                *reinterpret_cast<float2*>(A + i * 200 + 2 * j) = unpack2(acc[i][j]);
    }
}

template <int Cin, int Cout, int OT>
__device__ __forceinline__ void run_layer(float* sm, const float* __restrict__ gw, int tid)
{
    sconv_step<Cin, Cout, OT>(sm, gw, tid);
    __syncthreads();
    constexpr int CH = (Cout < 32) ? Cout : 32;
#pragma unroll
    for (int ch0 = 0; ch0 < Cout; ch0 += 32) {
        gemm1_step<CH>(sm, ch0, tid);
        __syncthreads();
        gemm2_step<CH>(sm, ch0, tid);
        __syncthreads();
    }
}

extern "C" __global__ void __launch_bounds__(NT, 1)
scnn_kernel(const float* __restrict__ x, const float* __restrict__ sft,
            const float* __restrict__ isft,
            const float* __restrict__ w1, const float* __restrict__ w2,
            const float* __restrict__ w3, const float* __restrict__ w4,
            const float* __restrict__ w5, const float* __restrict__ w6,
            float* __restrict__ out)
{
    extern __shared__ float sm[];
    const int tid = threadIdx.x;

    // ---- stage SFT/ISF transposed (+zero pads) ----
    for (int i = tid; i < 90 * 48; i += NT) {          // SFT[p][k], zero k>=45
        int p = i / 48, k = i - p * 48;
        sm[OFF_SFT + i] = (k < 45) ? sft[k * 90 + p] : 0.f;
    }
    for (int i = tid; i < 45 * 92; i += NT) {          // ISF[k][p], zero p>=90
        int k = i / 92, p = i - k * 92;
        sm[OFF_ISF + i] = (p < 90) ? isft[p * 45 + k] : 0.f;
    }
    if (tid < 45) {
        int k = tid;
        int d = (k >= 28) ? 4 : (k >= 15) ? 3 : (k >= 6) ? 2 : (k >= 1) ? 1 : 0;
        sm[OFF_SC + k] = sqrtf(3.14159265358979323846f / (float)(4 * d + 1));
    }
    __syncthreads();

    // ---- persistent stride loop over batch quads ----
    for (int quad = blockIdx.x; quad < NQUAD; quad += gridDim.x) {
        const int b0 = quad * BT;

        // load x: interleaved rows [c*4+bi][50]
        for (int i = tid; i < BT * 4 * 48; i += NT) {
            int bi = i / 192, r = i - bi * 192;
            int c = r / 48, k = r - c * 48;
            float v = 0.f;
            if (k < 45) v = x[(b0 + bi) * 180 + c * 45 + k];
            sm[OFF_A + (c * 4 + bi) * 50 + k] = v;
        }
        __syncthreads();

        run_layer<4,  16, 2>(sm, w1, tid);
        run_layer<16, 32, 4>(sm, w2, tid);
        run_layer<32, 64, 8>(sm, w3, tid);
        run_layer<64, 32, 4>(sm, w4, tid);
        run_layer<32, 16, 2>(sm, w5, tid);
        run_layer<16, 4,  1>(sm, w6, tid);

        // store output
        for (int i = tid; i < BT * 180; i += NT) {
            int bi = i / 180, r = i - bi * 180;
            int c = r / 45, k = r - c * 45;
            out[(b0 + bi) * 180 + r] = sm[OFF_A + (c * 4 + bi) * 50 + k];
        }
        __syncthreads();   // protect bufA before next iteration's load
    }
}

extern "C" void kernel_launch(void* const* d_in, const int* in_sizes, int n_in,
                              void* d_out, int out_size)
{
    cudaFuncSetAttribute(scnn_kernel, cudaFuncAttributeMaxDynamicSharedMemorySize,
                         SMEM_BYTES);
    scnn_kernel<<<NBLK, NT, SMEM_BYTES>>>(
        (const float*)d_in[0], (const float*)d_in[1], (const float*)d_in[2],
        (const float*)d_in[3], (const float*)d_in[4], (const float*)d_in[5],
        (const float*)d_in[6], (const float*)d_in[7], (const float*)d_in[8],
        (float*)d_out);
}

// round 8
// speedup vs baseline: 1.7234x; 1.0611x over previous
#include <cuda_runtime.h>
#include <math.h>

#define NT    512
#define NBLK  592
#define BATCH 50000
#define BT    4
#define NQUAD (BATCH / BT)

typedef unsigned long long u64;

// ---- shared memory layout (float offsets) ----
// Interleaved rows: row = ch*4 + bi. EVEN strides (float2-aligned) chosen so
// bi-deltas 1..3 map to distinct banks: 50 -> {18,4,22}, 94 -> {30,28,26}.
#define OFF_SFT  0            // SFT[p][k]: 90 x 48 (k>=45 zero)
#define OFF_ISF  4320         // ISF[k][p]: 45 x 92 (p>=90 zero)
#define OFF_SC   8460         // scale[45] (pad 48)
#define OFF_A    8508         // x buffer  [256 rows][50]  row = ch*4+bi, ch<64
#define OFF_B    21308        // t buffer  [256 rows][50]
#define OFF_SIG  34108        // sig       [128 rows][94]  row = ch*4+bi, ch<32
#define SMEM_FLOATS 46140
#define SMEM_BYTES  (SMEM_FLOATS * 4)

static_assert(OFF_SIG + 128 * 94 == SMEM_FLOATS, "smem layout");
static_assert((OFF_A & 1) == 0 && (OFF_B & 1) == 0 && (OFF_SIG & 1) == 0, "align");

// packed fp32x2 helpers
__device__ __forceinline__ u64 fma2(u64 a, u64 b, u64 c) {
    u64 d;
    asm("fma.rn.f32x2 %0, %1, %2, %3;" : "=l"(d) : "l"(a), "l"(b), "l"(c));
    return d;
}
__device__ __forceinline__ u64 pack2(float v) {
    u64 d;
    asm("mov.b64 %0, {%1, %1};" : "=l"(d) : "f"(v));
    return d;
}
__device__ __forceinline__ float2 unpack2(u64 v) {
    float2 r;
    asm("mov.b64 {%0, %1}, %2;" : "=f"(r.x), "=f"(r.y) : "l"(v));
    return r;
}

// sconv k-tiles aligned to degree-group boundaries (single ls_idx per tile)
__constant__ int c_tk0[15] = {0, 1, 5, 6, 10, 14, 15, 19, 23, 27, 28, 32, 36, 40, 44};
__constant__ int c_tkl[15] = {1, 4, 1, 4, 4, 1, 4, 4, 4, 1, 4, 4, 4, 4, 1};
__constant__ int c_td[15]  = {0, 1, 1, 2, 2, 2, 3, 3, 3, 3, 4, 4, 4, 4, 4};

// sconv: t[bi][o][k] = scale[k] * sum_c x[bi][c][k] * W[o][c][d(k)]
template <int Cin, int Cout, int OT>
__device__ __forceinline__ void sconv_step(float* sm, const float* __restrict__ gw, int tid)
{
    constexpr int SLOTS = BT * (Cout / OT) * 15;
    if (tid < SLOTS) {
        const int kt = tid % 15;
        const int bi = (tid / 15) & 3;
        const int ot = tid / (15 * BT);
        const int k0   = c_tk0[kt];
        const int klen = c_tkl[kt];
        const int d    = c_td[kt];
        const float* __restrict__ A = sm + OFF_A + bi * 50 + k0;      // +c*200
        const float* __restrict__ W = gw + (ot * OT) * (Cin * 5) + d;

        float acc[OT][4];
#pragma unroll
        for (int i = 0; i < OT; i++)
#pragma unroll
            for (int j = 0; j < 4; j++) acc[i][j] = 0.f;

#pragma unroll 4
        for (int c = 0; c < Cin; c++) {
            float xv[4];
#pragma unroll
            for (int j = 0; j < 4; j++) xv[j] = A[c * 200 + j];   // k0+3 <= 47 safe
#pragma unroll
            for (int i = 0; i < OT; i++) {
                float w = __ldg(W + i * (Cin * 5) + c * 5);
#pragma unroll
                for (int j = 0; j < 4; j++) acc[i][j] = fmaf(w, xv[j], acc[i][j]);
            }
        }

        float* __restrict__ B = sm + OFF_B + ((ot * OT) * 4 + bi) * 50 + k0;
#pragma unroll
        for (int i = 0; i < OT; i++)
#pragma unroll
            for (int j = 0; j < 4; j++)
                if (j < klen) B[i * 200 + j] = acc[i][j] * sm[OFF_SC + k0 + j];
    }
}

// GEMM1 (f32x2): sig[row][p0..p0+5] = relu( sum_k t[row][k] * ISF[k][p] )
// broadcast operand T loaded as float2 pairs (k even-aligned) -> 10 LDS / 2 k-iters
template <int NCH>
__device__ __forceinline__ void gemm1_step(float* sm, int ch0, int tid)
{
    constexpr int SLOTS = BT * (NCH / 4) * 15;
    if (tid < SLOTS) {
        const int pt = tid % 15;
        const int bi = (tid / 15) & 3;
        const int ct = tid / (15 * BT);
        const float* __restrict__ T  = sm + OFF_B + ((ch0 + ct * 4) * 4 + bi) * 50;
        const float* __restrict__ IS = sm + OFF_ISF + pt * 6;   // row step 92

        u64 acc[4][3];
#pragma unroll
        for (int i = 0; i < 4; i++)
#pragma unroll
            for (int j = 0; j < 3; j++) acc[i][j] = 0ull;

#pragma unroll 2
        for (int k2 = 0; k2 < 22; k2++) {
            const int k = 2 * k2;
            u64 iv0[3], iv1[3];
#pragma unroll
            for (int j = 0; j < 3; j++) {
                iv0[j] = *reinterpret_cast<const u64*>(IS + k * 92 + 2 * j);
                iv1[j] = *reinterpret_cast<const u64*>(IS + (k + 1) * 92 + 2 * j);
            }
#pragma unroll
            for (int i = 0; i < 4; i++) {
                float2 tp = *reinterpret_cast<const float2*>(T + i * 200 + k);
                u64 x0 = pack2(tp.x);
                u64 x1 = pack2(tp.y);
#pragma unroll
                for (int j = 0; j < 3; j++) {
                    acc[i][j] = fma2(x0, iv0[j], acc[i][j]);
                    acc[i][j] = fma2(x1, iv1[j], acc[i][j]);
                }
            }
        }
        {   // k = 44 tail
            u64 iv[3];
#pragma unroll
            for (int j = 0; j < 3; j++)
                iv[j] = *reinterpret_cast<const u64*>(IS + 44 * 92 + 2 * j);
#pragma unroll
            for (int i = 0; i < 4; i++) {
                u64 xp = pack2(T[i * 200 + 44]);
#pragma unroll
                for (int j = 0; j < 3; j++) acc[i][j] = fma2(xp, iv[j], acc[i][j]);
            }
        }

        float* __restrict__ S = sm + OFF_SIG + ((ct * 4) * 4 + bi) * 94 + pt * 6;
#pragma unroll
        for (int i = 0; i < 4; i++)
#pragma unroll
            for (int j = 0; j < 3; j++) {
                float2 r = unpack2(acc[i][j]);
                r.x = fmaxf(r.x, 0.f);
                r.y = fmaxf(r.y, 0.f);
                *reinterpret_cast<float2*>(S + i * 376 + 2 * j) = r;   // 4*94
            }
    }
}

// GEMM2 (f32x2): x[row][k0..k0+5] = sum_p sig[row][p] * SFT[p][k]
// broadcast operand S loaded as float2 pairs (p even-aligned); 90 = 45 pairs
template <int NCH>
__device__ __forceinline__ void gemm2_step(float* sm, int ch0, int tid)
{
    constexpr int SLOTS = BT * (NCH / 4) * 8;
    if (tid < SLOTS) {
        const int kt = tid % 8;
        const int bi = (tid / 8) & 3;
        const int ct = tid / (8 * BT);
        const int k0 = kt * 6;
        const float* __restrict__ S = sm + OFF_SIG + ((ct * 4) * 4 + bi) * 94;
        const float* __restrict__ F = sm + OFF_SFT + k0;        // row step 48

        u64 acc[4][3];
#pragma unroll
        for (int i = 0; i < 4; i++)
#pragma unroll
            for (int j = 0; j < 3; j++) acc[i][j] = 0ull;

#pragma unroll 3
        for (int p2 = 0; p2 < 45; p2++) {
            const int p = 2 * p2;
            u64 fv0[3], fv1[3];
#pragma unroll
            for (int j = 0; j < 3; j++) {
                fv0[j] = *reinterpret_cast<const u64*>(F + p * 48 + 2 * j);
                fv1[j] = *reinterpret_cast<const u64*>(F + (p + 1) * 48 + 2 * j);
            }
#pragma unroll
            for (int i = 0; i < 4; i++) {
                float2 sp = *reinterpret_cast<const float2*>(S + i * 376 + p);  // 4*94
                u64 s0 = pack2(sp.x);
                u64 s1 = pack2(sp.y);
#pragma unroll
                for (int j = 0; j < 3; j++) {
                    acc[i][j] = fma2(s0, fv0[j], acc[i][j]);
                    acc[i][j] = fma2(s1, fv1[j], acc[i][j]);
                }
            }
        }

        float* __restrict__ A = sm + OFF_A + ((ch0 + ct * 4) * 4 + bi) * 50 + k0;
#pragma unroll
        for (int i = 0; i < 4; i++)
#pragma unroll
            for (int j = 0; j < 3; j++)
                *reinterpret_cast<float2*>(A + i * 200 + 2 * j) = unpack2(acc[i][j]);
    }
}

template <int Cin, int Cout, int OT>
__device__ __forceinline__ void run_layer(float* sm, const float* __restrict__ gw, int tid)
{
    sconv_step<Cin, Cout, OT>(sm, gw, tid);
    __syncthreads();
    constexpr int CH = (Cout < 32) ? Cout : 32;
#pragma unroll
    for (int ch0 = 0; ch0 < Cout; ch0 += 32) {
        gemm1_step<CH>(sm, ch0, tid);
        __syncthreads();
        gemm2_step<CH>(sm, ch0, tid);
        __syncthreads();
    }
}

extern "C" __global__ void __launch_bounds__(NT, 1)
scnn_kernel(const float* __restrict__ x, const float* __restrict__ sft,
            const float* __restrict__ isft,
            const float* __restrict__ w1, const float* __restrict__ w2,
            const float* __restrict__ w3, const float* __restrict__ w4,
            const float* __restrict__ w5, const float* __restrict__ w6,
            float* __restrict__ out)
{
    extern __shared__ float sm[];
    const int tid = threadIdx.x;

    // ---- stage SFT/ISF transposed (+zero pads) ----
    for (int i = tid; i < 90 * 48; i += NT) {          // SFT[p][k], zero k>=45
        int p = i / 48, k = i - p * 48;
        sm[OFF_SFT + i] = (k < 45) ? sft[k * 90 + p] : 0.f;
    }
    for (int i = tid; i < 45 * 92; i += NT) {          // ISF[k][p], zero p>=90
        int k = i / 92, p = i - k * 92;
        sm[OFF_ISF + i] = (p < 90) ? isft[p * 45 + k] : 0.f;
    }
    if (tid < 45) {
        int k = tid;
        int d = (k >= 28) ? 4 : (k >= 15) ? 3 : (k >= 6) ? 2 : (k >= 1) ? 1 : 0;
        sm[OFF_SC + k] = sqrtf(3.14159265358979323846f / (float)(4 * d + 1));
    }
    __syncthreads();

    // ---- persistent stride loop over batch quads ----
    for (int quad = blockIdx.x; quad < NQUAD; quad += gridDim.x) {
        const int b0 = quad * BT;

        // load x: interleaved rows [c*4+bi][50]
        for (int i = tid; i < BT * 4 * 48; i += NT) {
            int bi = i / 192, r = i - bi * 192;
            int c = r / 48, k = r - c * 48;
            float v = 0.f;
            if (k < 45) v = x[(b0 + bi) * 180 + c * 45 + k];
            sm[OFF_A + (c * 4 + bi) * 50 + k] = v;
        }
        __syncthreads();

        run_layer<4,  16, 2>(sm, w1, tid);
        run_layer<16, 32, 4>(sm, w2, tid);
        run_layer<32, 64, 8>(sm, w3, tid);
        run_layer<64, 32, 4>(sm, w4, tid);
        run_layer<32, 16, 2>(sm, w5, tid);
        run_layer<16, 4,  1>(sm, w6, tid);

        // store output
        for (int i = tid; i < BT * 180; i += NT) {
            int bi = i / 180, r = i - bi * 180;
            int c = r / 45, k = r - c * 45;
            out[(b0 + bi) * 180 + r] = sm[OFF_A + (c * 4 + bi) * 50 + k];
        }
        __syncthreads();   // protect bufA before next iteration's load
    }
}

extern "C" void kernel_launch(void* const* d_in, const int* in_sizes, int n_in,
                              void* d_out, int out_size)
{
    cudaFuncSetAttribute(scnn_kernel, cudaFuncAttributeMaxDynamicSharedMemorySize,
                         SMEM_BYTES);
    scnn_kernel<<<NBLK, NT, SMEM_BYTES>>>(
        (const float*)d_in[0], (const float*)d_in[1], (const float*)d_in[2],
        (const float*)d_in[3], (const float*)d_in[4], (const float*)d_in[5],
        (const float*)d_in[6], (const float*)d_in[7], (const float*)d_in[8],
        (float*)d_out);
}

// round 9
// speedup vs baseline: 1.9689x; 1.1424x over previous
#include <cuda_runtime.h>
#include <math.h>

#define NT    512
#define NBLK  592
#define BATCH 50000
#define BT    4
#define NQUAD (BATCH / BT)

// ---- shared memory layout (float offsets) ----
#define O_IHI 0        // ISFT hi [p=96][k, stride 52]   (isft transposed-ish: [p][k])
#define O_ILO 4992     // ISFT lo
#define O_SHI 9984     // SFTT hi [k=48][p, stride 100]  ([k][p])
#define O_SLO 14784    // SFTT lo
#define O_SC  19584    // scale[45] (pad 48)
#define O_A   19632    // x/out buffer [256 rows][46]   row = ch*4+bi
#define O_T   31408    // sconv out    [256 rows][52]   row = och*4+bi, cols 45..51 zero
#define O_SIG 44720    // sig          [128 rows][100]
#define SMEM_FLOATS 57520
#define SMEM_BYTES  (SMEM_FLOATS * 4)

#define SA 46
#define ST 52
#define SS 100

// ---- tf32 helpers ----
__device__ __forceinline__ void split_tf32(float x, unsigned &hi, unsigned &lo) {
    asm("cvt.rna.tf32.f32 %0, %1;" : "=r"(hi) : "f"(x));
    float l = x - __uint_as_float(hi);
    asm("cvt.rna.tf32.f32 %0, %1;" : "=r"(lo) : "f"(l));
}
__device__ __forceinline__ void mma8(float d[4], const unsigned a[4], const unsigned b[2]) {
    asm volatile(
        "mma.sync.aligned.m16n8k8.row.col.f32.tf32.tf32.f32 "
        "{%0,%1,%2,%3}, {%4,%5,%6,%7}, {%8,%9}, {%0,%1,%2,%3};"
        : "+f"(d[0]), "+f"(d[1]), "+f"(d[2]), "+f"(d[3])
        : "r"(a[0]), "r"(a[1]), "r"(a[2]), "r"(a[3]), "r"(b[0]), "r"(b[1]));
}

// sconv k-tiles aligned to degree-group boundaries (single ls_idx per tile)
__constant__ int c_tk0[15] = {0, 1, 5, 6, 10, 14, 15, 19, 23, 27, 28, 32, 36, 40, 44};
__constant__ int c_tkl[15] = {1, 4, 1, 4, 4, 1, 4, 4, 4, 1, 4, 4, 4, 4, 1};
__constant__ int c_td[15]  = {0, 1, 1, 2, 2, 2, 3, 3, 3, 3, 4, 4, 4, 4, 4};

// sconv: T[och*4+bi][k] = scale[k] * sum_c A[c*4+bi][k] * W[och][c][d(k)]
template <int Cin, int Cout, int OT>
__device__ __forceinline__ void sconv_step(float* sm, const float* __restrict__ gw, int tid)
{
    constexpr int SLOTS = BT * (Cout / OT) * 15;
    if (tid < SLOTS) {
        const int kt = tid % 15;
        const int bi = (tid / 15) & 3;
        const int ot = tid / (15 * BT);
        const int k0   = c_tk0[kt];
        const int klen = c_tkl[kt];
        const int d    = c_td[kt];
        const float* __restrict__ A = sm + O_A + bi * SA + k0;      // + c*4*SA
        const float* __restrict__ W = gw + (ot * OT) * (Cin * 5) + d;

        float acc[OT][4];
#pragma unroll
        for (int i = 0; i < OT; i++)
#pragma unroll
            for (int j = 0; j < 4; j++) acc[i][j] = 0.f;

#pragma unroll 4
        for (int c = 0; c < Cin; c++) {
            float xv[4];
#pragma unroll
            for (int j = 0; j < 4; j++) xv[j] = A[c * (4 * SA) + j];
#pragma unroll
            for (int i = 0; i < OT; i++) {
                float w = __ldg(W + i * (Cin * 5) + c * 5);
#pragma unroll
                for (int j = 0; j < 4; j++) acc[i][j] = fmaf(w, xv[j], acc[i][j]);
            }
        }

        float* __restrict__ Tp = sm + O_T + ((ot * OT) * 4 + bi) * ST + k0;
#pragma unroll
        for (int i = 0; i < OT; i++)
#pragma unroll
            for (int j = 0; j < 4; j++)
                if (j < klen) Tp[i * (4 * ST) + j] = acc[i][j] * sm[O_SC + k0 + j];
    }
}

// GEMM1 (MMA): sig[m][n=p] = relu( sum_k T[trow0+m][k] * ISF[k][p] ),  K=48, N=96
// warp grid 4m x 4n; warp covers MT m16-tiles x 24 n-cols.
template <int MT, int MW>
__device__ __forceinline__ void gemm1_mma(float* sm, int trow0, int w, int lane)
{
    const int mw = w & 3, nw = w >> 2;
    if (mw < MW) {
        const int g = lane >> 2, t = lane & 3;
        float d[MT][3][4];
#pragma unroll
        for (int i = 0; i < MT; i++)
#pragma unroll
            for (int nt = 0; nt < 3; nt++)
#pragma unroll
                for (int r = 0; r < 4; r++) d[i][nt][r] = 0.f;

        const float* Tb = sm + O_T + trow0 * ST;
#pragma unroll
        for (int kc = 0; kc < 6; kc++) {
            const int k0 = kc * 8;
            unsigned ahi[MT][4], alo[MT][4];
#pragma unroll
            for (int i = 0; i < MT; i++) {
                const int m0 = (mw * MT + i) * 16;
                float a0 = Tb[(m0 + g) * ST + k0 + t];
                float a1 = Tb[(m0 + g + 8) * ST + k0 + t];
                float a2 = Tb[(m0 + g) * ST + k0 + t + 4];
                float a3 = Tb[(m0 + g + 8) * ST + k0 + t + 4];
                split_tf32(a0, ahi[i][0], alo[i][0]);
                split_tf32(a1, ahi[i][1], alo[i][1]);
                split_tf32(a2, ahi[i][2], alo[i][2]);
                split_tf32(a3, ahi[i][3], alo[i][3]);
            }
#pragma unroll
            for (int nt = 0; nt < 3; nt++) {
                const int n0 = nw * 24 + nt * 8;
                unsigned bh[2], bl[2];
                bh[0] = __float_as_uint(sm[O_IHI + (n0 + g) * ST + k0 + t]);
                bh[1] = __float_as_uint(sm[O_IHI + (n0 + g) * ST + k0 + t + 4]);
                bl[0] = __float_as_uint(sm[O_ILO + (n0 + g) * ST + k0 + t]);
                bl[1] = __float_as_uint(sm[O_ILO + (n0 + g) * ST + k0 + t + 4]);
#pragma unroll
                for (int i = 0; i < MT; i++) {
                    mma8(d[i][nt], ahi[i], bh);
                    mma8(d[i][nt], ahi[i], bl);
                    mma8(d[i][nt], alo[i], bh);
                }
            }
        }
        // epilogue: relu -> sig
#pragma unroll
        for (int i = 0; i < MT; i++) {
            const int m0 = (mw * MT + i) * 16;
#pragma unroll
            for (int nt = 0; nt < 3; nt++) {
                const int n0 = nw * 24 + nt * 8;
                float2 v0 = make_float2(fmaxf(d[i][nt][0], 0.f), fmaxf(d[i][nt][1], 0.f));
                float2 v1 = make_float2(fmaxf(d[i][nt][2], 0.f), fmaxf(d[i][nt][3], 0.f));
                *reinterpret_cast<float2*>(sm + O_SIG + (m0 + g) * SS + n0 + 2 * t) = v0;
                *reinterpret_cast<float2*>(sm + O_SIG + (m0 + g + 8) * SS + n0 + 2 * t) = v1;
            }
        }
    }
}

// GEMM2 (MMA): A[arow0+m][n=kout] = sum_p sig[m][p] * SFT[p][kout],  K=96, N=48
// warp grid 8m x 2n; warp covers 1 m16-tile x 24 n-cols. sig split on load.
template <int MW2>
__device__ __forceinline__ void gemm2_mma(float* sm, int arow0, int w, int lane)
{
    const int mw = w >> 1, nw = w & 1;
    if (mw < MW2) {
        const int g = lane >> 2, t = lane & 3;
        const int m0 = mw * 16;
        float d[3][4];
#pragma unroll
        for (int nt = 0; nt < 3; nt++)
#pragma unroll
            for (int r = 0; r < 4; r++) d[nt][r] = 0.f;

#pragma unroll
        for (int pc = 0; pc < 12; pc++) {
            const int p0 = pc * 8;
            unsigned ahi[4], alo[4];
            float a0 = sm[O_SIG + (m0 + g) * SS + p0 + t];
            float a1 = sm[O_SIG + (m0 + g + 8) * SS + p0 + t];
            float a2 = sm[O_SIG + (m0 + g) * SS + p0 + t + 4];
            float a3 = sm[O_SIG + (m0 + g + 8) * SS + p0 + t + 4];
            split_tf32(a0, ahi[0], alo[0]);
            split_tf32(a1, ahi[1], alo[1]);
            split_tf32(a2, ahi[2], alo[2]);
            split_tf32(a3, ahi[3], alo[3]);
#pragma unroll
            for (int nt = 0; nt < 3; nt++) {
                const int n0 = nw * 24 + nt * 8;
                unsigned bh[2], bl[2];
                bh[0] = __float_as_uint(sm[O_SHI + (n0 + g) * SS + p0 + t]);
                bh[1] = __float_as_uint(sm[O_SHI + (n0 + g) * SS + p0 + t + 4]);
                bl[0] = __float_as_uint(sm[O_SLO + (n0 + g) * SS + p0 + t]);
                bl[1] = __float_as_uint(sm[O_SLO + (n0 + g) * SS + p0 + t + 4]);
                mma8(d[nt], ahi, bh);
                mma8(d[nt], ahi, bl);
                mma8(d[nt], alo, bh);
            }
        }
        // epilogue: store to A (cols 0..45 valid; 46,47 are zero cols -> skipped)
#pragma unroll
        for (int nt = 0; nt < 3; nt++) {
            const int n0 = nw * 24 + nt * 8;
            const int col = n0 + 2 * t;
            if (col < 46) {
                *reinterpret_cast<float2*>(sm + O_A + (arow0 + m0 + g) * SA + col) =
                    make_float2(d[nt][0], d[nt][1]);
                *reinterpret_cast<float2*>(sm + O_A + (arow0 + m0 + g + 8) * SA + col) =
                    make_float2(d[nt][2], d[nt][3]);
            }
        }
    }
}

template <int Cin, int Cout, int OT>
__device__ __forceinline__ void run_layer(float* sm, const float* __restrict__ gw, int tid)
{
    sconv_step<Cin, Cout, OT>(sm, gw, tid);
    __syncthreads();
    const int w = tid >> 5, lane = tid & 31;
    constexpr int NCHB = (Cout + 31) / 32;
    constexpr int M = 4 * (Cout < 32 ? Cout : 32);
#pragma unroll
    for (int cb = 0; cb < NCHB; cb++) {
        if constexpr (M == 128)      gemm1_mma<2, 4>(sm, cb * 128, w, lane);
        else if constexpr (M == 64)  gemm1_mma<1, 4>(sm, 0, w, lane);
        else                         gemm1_mma<1, 1>(sm, 0, w, lane);
        __syncthreads();
        if constexpr (M == 128)      gemm2_mma<8>(sm, cb * 128, w, lane);
        else if constexpr (M == 64)  gemm2_mma<4>(sm, 0, w, lane);
        else                         gemm2_mma<1>(sm, 0, w, lane);
        __syncthreads();
    }
}

extern "C" __global__ void __launch_bounds__(NT, 1)
scnn_kernel(const float* __restrict__ x, const float* __restrict__ sft,
            const float* __restrict__ isft,
            const float* __restrict__ w1, const float* __restrict__ w2,
            const float* __restrict__ w3, const float* __restrict__ w4,
            const float* __restrict__ w5, const float* __restrict__ w6,
            float* __restrict__ out)
{
    extern __shared__ float sm[];
    const int tid = threadIdx.x;

    // ---- stage ISFT hi/lo: [p][k], stride 52, zero pads (p>=90 or k>=45) ----
    for (int i = tid; i < 96 * 48; i += NT) {
        int p = i / 48, k = i - p * 48;
        float v = (p < 90 && k < 45) ? isft[p * 45 + k] : 0.f;
        unsigned h, l; split_tf32(v, h, l);
        sm[O_IHI + p * ST + k] = __uint_as_float(h);
        sm[O_ILO + p * ST + k] = __uint_as_float(l);
    }
    // ---- stage SFTT hi/lo: [k][p], stride 100, zero pads ----
    for (int i = tid; i < 48 * 96; i += NT) {
        int k = i / 96, p = i - k * 96;
        float v = (k < 45 && p < 90) ? sft[k * 90 + p] : 0.f;
        unsigned h, l; split_tf32(v, h, l);
        sm[O_SHI + k * SS + p] = __uint_as_float(h);
        sm[O_SLO + k * SS + p] = __uint_as_float(l);
    }
    if (tid < 45) {
        int k = tid;
        int dd = (k >= 28) ? 4 : (k >= 15) ? 3 : (k >= 6) ? 2 : (k >= 1) ? 1 : 0;
        sm[O_SC + k] = sqrtf(3.14159265358979323846f / (float)(4 * dd + 1));
    }
    // ---- zero T pad cols 45..51 for all 256 rows (sconv never writes them) ----
    for (int i = tid; i < 256 * 7; i += NT) {
        int r = i / 7, c = 45 + (i - (i / 7) * 7);
        sm[O_T + r * ST + c] = 0.f;
    }
    __syncthreads();

    // ---- persistent stride loop over batch quads ----
    for (int quad = blockIdx.x; quad < NQUAD; quad += gridDim.x) {
        const int b0 = quad * BT;

        // load x: rows c*4+bi, cols 0..44
        for (int i = tid; i < BT * 4 * 45; i += NT) {
            int bi = i / 180, r = i - bi * 180;
            int c = r / 45, k = r - c * 45;
            sm[O_A + (c * 4 + bi) * SA + k] = x[(b0 + bi) * 180 + r];
        }
        __syncthreads();

        run_layer<4,  16, 2>(sm, w1, tid);
        run_layer<16, 32, 4>(sm, w2, tid);
        run_layer<32, 64, 8>(sm, w3, tid);
        run_layer<64, 32, 4>(sm, w4, tid);
        run_layer<32, 16, 2>(sm, w5, tid);
        run_layer<16, 4,  1>(sm, w6, tid);

        // store output
        for (int i = tid; i < BT * 180; i += NT) {
            int bi = i / 180, r = i - bi * 180;
            int c = r / 45, k = r - c * 45;
            out[(b0 + bi) * 180 + r] = sm[O_A + (c * 4 + bi) * SA + k];
        }
        __syncthreads();   // protect A before next iteration's load
    }
}

extern "C" void kernel_launch(void* const* d_in, const int* in_sizes, int n_in,
                              void* d_out, int out_size)
{
    cudaFuncSetAttribute(scnn_kernel, cudaFuncAttributeMaxDynamicSharedMemorySize,
                         SMEM_BYTES);
    scnn_kernel<<<NBLK, NT, SMEM_BYTES>>>(
        (const float*)d_in[0], (const float*)d_in[1], (const float*)d_in[2],
        (const float*)d_in[3], (const float*)d_in[4], (const float*)d_in[5],
        (const float*)d_in[6], (const float*)d_in[7], (const float*)d_in[8],
        (float*)d_out);
}

// round 10
// speedup vs baseline: 2.1500x; 1.0920x over previous
#include <cuda_runtime.h>
#include <math.h>

#define NT    512
#define NBLK  592
#define BATCH 50000
#define BT    4
#define NQUAD (BATCH / BT)

// ---- shared memory layout (float offsets) ----
#define O_IHI 0        // ISFT hi [p=96][k, stride 52]
#define O_ILO 4992     // ISFT lo
#define O_SHI 9984     // SFTT hi [k=48][p, stride 100]
#define O_SLO 14784    // SFTT lo
#define O_SC  19584    // scale[45] (pad 48)
#define O_A   19632    // x / gemm2-out / T-lo buffer [256 rows][46]
#define O_T   31408    // sconv out hi [256 rows][52], cols 45..51 zero
#define O_SIG 44720    // sig          [128 rows][100]
#define SMEM_FLOATS 57520
#define SMEM_BYTES  (SMEM_FLOATS * 4)

#define SA 46
#define ST 52
#define SS 100

// ---- tf32 helpers: truncation split (LOP3 + FADD, no cvt chains) ----
__device__ __forceinline__ void split_tf32(float x, unsigned &hi, unsigned &lo) {
    unsigned xb = __float_as_uint(x);
    hi = xb & 0xFFFFE000u;
    lo = __float_as_uint(x - __uint_as_float(hi));
}
__device__ __forceinline__ void mma8(float d[4], const unsigned a[4], const unsigned b[2]) {
    asm volatile(
        "mma.sync.aligned.m16n8k8.row.col.f32.tf32.tf32.f32 "
        "{%0,%1,%2,%3}, {%4,%5,%6,%7}, {%8,%9}, {%0,%1,%2,%3};"
        : "+f"(d[0]), "+f"(d[1]), "+f"(d[2]), "+f"(d[3])
        : "r"(a[0]), "r"(a[1]), "r"(a[2]), "r"(a[3]), "r"(b[0]), "r"(b[1]));
}

// sconv k-tiles aligned to degree-group boundaries (single ls_idx per tile)
__constant__ int c_tk0[15] = {0, 1, 5, 6, 10, 14, 15, 19, 23, 27, 28, 32, 36, 40, 44};
__constant__ int c_tkl[15] = {1, 4, 1, 4, 4, 1, 4, 4, 4, 1, 4, 4, 4, 4, 1};
__constant__ int c_td[15]  = {0, 1, 1, 2, 2, 2, 3, 3, 3, 3, 4, 4, 4, 4, 4};

// sconv: reads A (rows c*4+bi), writes T hi + T lo (lo into the A buffer).
// Internal barrier separates the A reads from the TLO writes (same buffer).
template <int Cin, int Cout, int OT>
__device__ __forceinline__ void sconv_step(float* sm, const float* __restrict__ gw, int tid)
{
    constexpr int SLOTS = BT * (Cout / OT) * 15;
    const int kt = tid % 15;
    const int bi = (tid / 15) & 3;
    const int ot = tid / (15 * BT);
    const int k0   = c_tk0[kt];
    const int klen = c_tkl[kt];
    const int d    = c_td[kt];

    float acc[OT][4];
#pragma unroll
    for (int i = 0; i < OT; i++)
#pragma unroll
        for (int j = 0; j < 4; j++) acc[i][j] = 0.f;

    if (tid < SLOTS) {
        const float* __restrict__ A = sm + O_A + bi * SA + k0;
        const float* __restrict__ W = gw + (ot * OT) * (Cin * 5) + d;
#pragma unroll 4
        for (int c = 0; c < Cin; c++) {
            float xv[4];
#pragma unroll
            for (int j = 0; j < 4; j++) xv[j] = A[c * (4 * SA) + j];
#pragma unroll
            for (int i = 0; i < OT; i++) {
                float w = __ldg(W + i * (Cin * 5) + c * 5);
#pragma unroll
                for (int j = 0; j < 4; j++) acc[i][j] = fmaf(w, xv[j], acc[i][j]);
            }
        }
    }
    __syncthreads();   // all A reads complete before TLO overwrites the buffer

    if (tid < SLOTS) {
        float* __restrict__ Th = sm + O_T + ((ot * OT) * 4 + bi) * ST + k0;
        float* __restrict__ Tl = sm + O_A + ((ot * OT) * 4 + bi) * SA + k0;
#pragma unroll
        for (int i = 0; i < OT; i++)
#pragma unroll
            for (int j = 0; j < 4; j++)
                if (j < klen) {
                    float v = acc[i][j] * sm[O_SC + k0 + j];
                    unsigned h, l; split_tf32(v, h, l);
                    Th[i * (4 * ST) + j] = __uint_as_float(h);
                    Tl[i * (4 * SA) + j] = __uint_as_float(l);
                }
    }
}

// GEMM1 (MMA): sig[m][p] = relu( sum_k T[trow0+m][k]*ISF[k][p] ), K=48, N=96
// a hi from T (stride 52), a lo pre-split in TLO (stride 46). No runtime split.
template <int MT, int MW>
__device__ __forceinline__ void gemm1_mma(float* sm, int trow0, int w, int lane)
{
    const int mw = w & 3, nw = w >> 2;
    if (mw < MW) {
        const int g = lane >> 2, t = lane & 3;
        float d[MT][3][4];
#pragma unroll
        for (int i = 0; i < MT; i++)
#pragma unroll
            for (int nt = 0; nt < 3; nt++)
#pragma unroll
                for (int r = 0; r < 4; r++) d[i][nt][r] = 0.f;

        const float* Tb = sm + O_T + trow0 * ST;
        const float* Lb = sm + O_A + trow0 * SA;
#pragma unroll
        for (int kc = 0; kc < 6; kc++) {
            const int k0 = kc * 8;
            unsigned ahi[MT][4], alo[MT][4];
#pragma unroll
            for (int i = 0; i < MT; i++) {
                const int m0 = (mw * MT + i) * 16;
                ahi[i][0] = __float_as_uint(Tb[(m0 + g) * ST + k0 + t]);
                ahi[i][1] = __float_as_uint(Tb[(m0 + g + 8) * ST + k0 + t]);
                ahi[i][2] = __float_as_uint(Tb[(m0 + g) * ST + k0 + t + 4]);
                ahi[i][3] = __float_as_uint(Tb[(m0 + g + 8) * ST + k0 + t + 4]);
                alo[i][0] = __float_as_uint(Lb[(m0 + g) * SA + k0 + t]);
                alo[i][1] = __float_as_uint(Lb[(m0 + g + 8) * SA + k0 + t]);
                if (kc < 5) {
                    alo[i][2] = __float_as_uint(Lb[(m0 + g) * SA + k0 + t + 4]);
                    alo[i][3] = __float_as_uint(Lb[(m0 + g + 8) * SA + k0 + t + 4]);
                } else {   // k = 44..47: only 44 valid in TLO (stride 46)
                    alo[i][2] = (t == 0) ? __float_as_uint(Lb[(m0 + g) * SA + 44]) : 0u;
                    alo[i][3] = (t == 0) ? __float_as_uint(Lb[(m0 + g + 8) * SA + 44]) : 0u;
                }
            }
#pragma unroll
            for (int nt = 0; nt < 3; nt++) {
                const int n0 = nw * 24 + nt * 8;
                unsigned bh[2], bl[2];
                bh[0] = __float_as_uint(sm[O_IHI + (n0 + g) * ST + k0 + t]);
                bh[1] = __float_as_uint(sm[O_IHI + (n0 + g) * ST + k0 + t + 4]);
                bl[0] = __float_as_uint(sm[O_ILO + (n0 + g) * ST + k0 + t]);
                bl[1] = __float_as_uint(sm[O_ILO + (n0 + g) * ST + k0 + t + 4]);
#pragma unroll
                for (int i = 0; i < MT; i++) {
                    mma8(d[i][nt], ahi[i], bh);
                    mma8(d[i][nt], ahi[i], bl);
                    mma8(d[i][nt], alo[i], bh);
                }
            }
        }
#pragma unroll
        for (int i = 0; i < MT; i++) {
            const int m0 = (mw * MT + i) * 16;
#pragma unroll
            for (int nt = 0; nt < 3; nt++) {
                const int n0 = nw * 24 + nt * 8;
                float2 v0 = make_float2(fmaxf(d[i][nt][0], 0.f), fmaxf(d[i][nt][1], 0.f));
                float2 v1 = make_float2(fmaxf(d[i][nt][2], 0.f), fmaxf(d[i][nt][3], 0.f));
                *reinterpret_cast<float2*>(sm + O_SIG + (m0 + g) * SS + n0 + 2 * t) = v0;
                *reinterpret_cast<float2*>(sm + O_SIG + (m0 + g + 8) * SS + n0 + 2 * t) = v1;
            }
        }
    }
}

// GEMM2 (MMA): A[arow0+m][k] = sum_p sig[m][p] * SFT[p][k], K=96, N=48
// sig split at load via mask+sub (2 fixed-lat ops).
template <int MW2>
__device__ __forceinline__ void gemm2_mma(float* sm, int arow0, int w, int lane)
{
    const int mw = w >> 1, nw = w & 1;
    if (mw < MW2) {
        const int g = lane >> 2, t = lane & 3;
        const int m0 = mw * 16;
        float d[3][4];
#pragma unroll
        for (int nt = 0; nt < 3; nt++)
#pragma unroll
            for (int r = 0; r < 4; r++) d[nt][r] = 0.f;

#pragma unroll
        for (int pc = 0; pc < 12; pc++) {
            const int p0 = pc * 8;
            unsigned ahi[4], alo[4];
            float a0 = sm[O_SIG + (m0 + g) * SS + p0 + t];
            float a1 = sm[O_SIG + (m0 + g + 8) * SS + p0 + t];
            float a2 = sm[O_SIG + (m0 + g) * SS + p0 + t + 4];
            float a3 = sm[O_SIG + (m0 + g + 8) * SS + p0 + t + 4];
            split_tf32(a0, ahi[0], alo[0]);
            split_tf32(a1, ahi[1], alo[1]);
            split_tf32(a2, ahi[2], alo[2]);
            split_tf32(a3, ahi[3], alo[3]);
#pragma unroll
            for (int nt = 0; nt < 3; nt++) {
                const int n0 = nw * 24 + nt * 8;
                unsigned bh[2], bl[2];
                bh[0] = __float_as_uint(sm[O_SHI + (n0 + g) * SS + p0 + t]);
                bh[1] = __float_as_uint(sm[O_SHI + (n0 + g) * SS + p0 + t + 4]);
                bl[0] = __float_as_uint(sm[O_SLO + (n0 + g) * SS + p0 + t]);
                bl[1] = __float_as_uint(sm[O_SLO + (n0 + g) * SS + p0 + t + 4]);
                mma8(d[nt], ahi, bh);
                mma8(d[nt], ahi, bl);
                mma8(d[nt], alo, bh);
            }
        }
#pragma unroll
        for (int nt = 0; nt < 3; nt++) {
            const int n0 = nw * 24 + nt * 8;
            const int col = n0 + 2 * t;
            if (col < 46) {
                *reinterpret_cast<float2*>(sm + O_A + (arow0 + m0 + g) * SA + col) =
                    make_float2(d[nt][0], d[nt][1]);
                *reinterpret_cast<float2*>(sm + O_A + (arow0 + m0 + g + 8) * SA + col) =
                    make_float2(d[nt][2], d[nt][3]);
            }
        }
    }
}

template <int Cin, int Cout, int OT>
__device__ __forceinline__ void run_layer(float* sm, const float* __restrict__ gw, int tid)
{
    sconv_step<Cin, Cout, OT>(sm, gw, tid);   // contains internal barrier
    __syncthreads();
    const int w = tid >> 5, lane = tid & 31;
    constexpr int NCHB = (Cout + 31) / 32;
    constexpr int M = 4 * (Cout < 32 ? Cout : 32);
#pragma unroll
    for (int cb = 0; cb < NCHB; cb++) {
        if constexpr (M == 128)      gemm1_mma<2, 4>(sm, cb * 128, w, lane);
        else if constexpr (M == 64)  gemm1_mma<1, 4>(sm, 0, w, lane);
        else                         gemm1_mma<1, 1>(sm, 0, w, lane);
        __syncthreads();
        if constexpr (M == 128)      gemm2_mma<8>(sm, cb * 128, w, lane);
        else if constexpr (M == 64)  gemm2_mma<4>(sm, 0, w, lane);
        else                         gemm2_mma<1>(sm, 0, w, lane);
        __syncthreads();
    }
}

extern "C" __global__ void __launch_bounds__(NT, 1)
scnn_kernel(const float* __restrict__ x, const float* __restrict__ sft,
            const float* __restrict__ isft,
            const float* __restrict__ w1, const float* __restrict__ w2,
            const float* __restrict__ w3, const float* __restrict__ w4,
            const float* __restrict__ w5, const float* __restrict__ w6,
            float* __restrict__ out)
{
    extern __shared__ float sm[];
    const int tid = threadIdx.x;

    // ---- stage ISFT hi/lo: [p][k], stride 52, zero pads ----
    for (int i = tid; i < 96 * 48; i += NT) {
        int p = i / 48, k = i - p * 48;
        float v = (p < 90 && k < 45) ? isft[p * 45 + k] : 0.f;
        unsigned h, l; split_tf32(v, h, l);
        sm[O_IHI + p * ST + k] = __uint_as_float(h);
        sm[O_ILO + p * ST + k] = __uint_as_float(l);
    }
    // ---- stage SFTT hi/lo: [k][p], stride 100, zero pads ----
    for (int i = tid; i < 48 * 96; i += NT) {
        int k = i / 96, p = i - k * 96;
        float v = (k < 45 && p < 90) ? sft[k * 90 + p] : 0.f;
        unsigned h, l; split_tf32(v, h, l);
        sm[O_SHI + k * SS + p] = __uint_as_float(h);
        sm[O_SLO + k * SS + p] = __uint_as_float(l);
    }
    if (tid < 45) {
        int k = tid;
        int dd = (k >= 28) ? 4 : (k >= 15) ? 3 : (k >= 6) ? 2 : (k >= 1) ? 1 : 0;
        sm[O_SC + k] = sqrtf(3.14159265358979323846f / (float)(4 * dd + 1));
    }
    // ---- zero T pad cols 45..51 (sconv never writes them) ----
    for (int i = tid; i < 256 * 7; i += NT) {
        int r = i / 7, c = 45 + (i - (i / 7) * 7);
        sm[O_T + r * ST + c] = 0.f;
    }
    __syncthreads();

    // ---- persistent stride loop over batch quads ----
    for (int quad = blockIdx.x; quad < NQUAD; quad += gridDim.x) {
        const int b0 = quad * BT;

        // load x: rows c*4+bi, cols 0..44
        for (int i = tid; i < BT * 4 * 45; i += NT) {
            int bi = i / 180, r = i - bi * 180;
            int c = r / 45, k = r - c * 45;
            sm[O_A + (c * 4 + bi) * SA + k] = x[(b0 + bi) * 180 + r];
        }
        __syncthreads();

        run_layer<4,  16, 2>(sm, w1, tid);
        run_layer<16, 32, 4>(sm, w2, tid);
        run_layer<32, 64, 8>(sm, w3, tid);
        run_layer<64, 32, 4>(sm, w4, tid);
        run_layer<32, 16, 2>(sm, w5, tid);
        run_layer<16, 4,  1>(sm, w6, tid);

        // store output
        for (int i = tid; i < BT * 180; i += NT) {
            int bi = i / 180, r = i - bi * 180;
            int c = r / 45, k = r - c * 45;
            out[(b0 + bi) * 180 + r] = sm[O_A + (c * 4 + bi) * SA + k];
        }
        __syncthreads();   // protect A before next iteration's load
    }
}

extern "C" void kernel_launch(void* const* d_in, const int* in_sizes, int n_in,
                              void* d_out, int out_size)
{
    cudaFuncSetAttribute(scnn_kernel, cudaFuncAttributeMaxDynamicSharedMemorySize,
                         SMEM_BYTES);
    scnn_kernel<<<NBLK, NT, SMEM_BYTES>>>(
        (const float*)d_in[0], (const float*)d_in[1], (const float*)d_in[2],
        (const float*)d_in[3], (const float*)d_in[4], (const float*)d_in[5],
        (const float*)d_in[6], (const float*)d_in[7], (const float*)d_in[8],
        (float*)d_out);
}